// round 11
// baseline (speedup 1.0000x reference)
#include <cuda_runtime.h>
#include <cuda_fp16.h>
#include <cstdint>
#include <math.h>

#define NN   4096
#define FFD  2048
#define KTOT 4096   // concat K: [h0 (2048) | behavior (2048)]

// ---------------- device scratch (no cudaMalloc allowed) -------------------
static __device__ __half g_A[(size_t)NN * KTOT];              // 33.5MB  A fp16
static __device__ __half g_W[(size_t)4 * FFD * KTOT];         // 67MB    W^T fp16 [g*FFD+n][k]

// ---------------- helpers ---------------------------------------------------
__device__ __forceinline__ uint32_t smem_u32(const void* p) {
    uint32_t a;
    asm("{ .reg .u64 t; cvta.to.shared.u64 t, %1; cvt.u32.u64 %0, t; }"
        : "=r"(a) : "l"(p));
    return a;
}
__device__ __forceinline__ void cpa16(uint32_t s, const void* g) {
    asm volatile("cp.async.cg.shared.global [%0], [%1], 16;" :: "r"(s), "l"(g));
}
#define CPA_COMMIT() asm volatile("cp.async.commit_group;" ::: "memory")
#define CPA_WAIT1()  asm volatile("cp.async.wait_group 1;" ::: "memory")

__device__ __forceinline__ void ldsm4(uint32_t* r, uint32_t addr) {
    asm volatile("ldmatrix.sync.aligned.m8n8.x4.shared.b16 {%0,%1,%2,%3}, [%4];"
                 : "=r"(r[0]), "=r"(r[1]), "=r"(r[2]), "=r"(r[3]) : "r"(addr));
}
__device__ __forceinline__ void mma16816(float* c, const uint32_t* a, const uint32_t* b) {
    asm volatile("mma.sync.aligned.m16n8k16.row.col.f32.f16.f16.f32 "
                 "{%0,%1,%2,%3}, {%4,%5,%6,%7}, {%8,%9}, {%0,%1,%2,%3};"
                 : "+f"(c[0]), "+f"(c[1]), "+f"(c[2]), "+f"(c[3])
                 : "r"(a[0]), "r"(a[1]), "r"(a[2]), "r"(a[3]),
                   "r"(b[0]), "r"(b[1]));
}

// ---------------- merged pre-pass: A convert + W transpose/convert ----------
__global__ __launch_bounds__(256)
void conv_AW_kernel(const float* __restrict__ h0, const float* __restrict__ beh,
                    const float* Wi_h, const float* Wi_x,
                    const float* Wf_h, const float* Wf_x,
                    const float* Wg_h, const float* Wg_x,
                    const float* Wo_h, const float* Wo_x)
{
    const int b = blockIdx.x;
    const int tid = threadIdx.x;

    if (b < 4096) {
        // ---- A conversion: 4 independent float4s per thread (MLP=4) ----
#pragma unroll
        for (int i = 0; i < 4; i++) {
            size_t e = ((size_t)b * 1024 + i * 256 + tid) * 4;
            int m = (int)(e >> 12);
            int k = (int)(e & 4095);
            const float* src = (k < 2048) ? (h0 + (size_t)m * 2048 + k)
                                          : (beh + (size_t)m * 2048 + (k - 2048));
            float4 v = *(const float4*)src;
            __half2* dh = (__half2*)(g_A + e);
            dh[0] = __halves2half2(__float2half_rn(v.x), __float2half_rn(v.y));
            dh[1] = __halves2half2(__float2half_rn(v.z), __float2half_rn(v.w));
        }
        return;
    }

    // ---- W transpose: src [K=2048][N=2048] fp32 -> g_W[(g*FFD+n)*KTOT + isx*2048 + k]
    const float* srcs[8] = {Wi_h, Wi_x, Wf_h, Wf_x, Wg_h, Wg_x, Wo_h, Wo_x};
    const int bb = b - 4096;
    const int z = bb >> 12;           // 0..7: matrix index
    const int t = bb & 4095;          // 64x64 tiles of 32x32
    const int g = z >> 1, isx = z & 1;
    const float* __restrict__ src = srcs[z];
    const int k0 = (t >> 6) * 32, n0 = (t & 63) * 32;

    __shared__ __half tt[32][33];     // [k_local][n_local], padded

    {   // phase 1: coalesced fp32 reads, convert, half to smem
        int n_l = tid & 31;
        int k_l = tid >> 5;           // 0..7
#pragma unroll
        for (int i = 0; i < 4; i++) {
            int kk = k_l + i * 8;
            tt[kk][n_l] = __float2half_rn(src[(size_t)(k0 + kk) * 2048 + n0 + n_l]);
        }
    }
    __syncthreads();

    {   // phase 2: pack 4 consecutive k for one n -> 8B store
        int n_l = tid >> 3;           // 0..31
        int k_q = (tid & 7) * 4;      // 0,4,...,28
        __half2 p0 = __halves2half2(tt[k_q + 0][n_l], tt[k_q + 1][n_l]);
        __half2 p1 = __halves2half2(tt[k_q + 2][n_l], tt[k_q + 3][n_l]);
        size_t o = ((size_t)g * FFD + n0 + n_l) * KTOT + isx * 2048 + k0 + k_q;
        __half2* dst = (__half2*)(g_W + o);
        dst[0] = p0;
        dst[1] = p1;
    }
}

// ---------------- fused 4-gate GEMM + LSTM epilogue -------------------------
// BM=128, BN=32 per gate (x4 gates), BK=64, 3 stages, 256 threads, 2 CTAs/SM.
// ONE __syncthreads per chunk: fill(c+2) placed after the top barrier, which
// already guarantees all warps finished chunk c-1 (the stage being refilled).
static constexpr int A_OFF    = 0;        // 128 rows x 128B = 16KB
static constexpr int WP_OFF   = 16384;    // 4 gates x 32 rows x 128B = 16KB
static constexpr int STAGE_SZ = 32768;    // 32KB
static constexpr int SMEM_TOTAL = 3 * STAGE_SZ;  // 96KB -> 2 CTAs/SM

__device__ __forceinline__ void fill_stage(uint32_t sb, int m0, int n0, int kb, int tid) {
#pragma unroll
    for (int i = 0; i < 4; i++) {               // A: 1024 16B units
        int u = tid + i * 256;
        int row = u >> 3, cu = u & 7;
        uint32_t sw = (uint32_t)(row * 128 + ((cu ^ (row & 7)) << 4));
        size_t go = (size_t)(m0 + row) * KTOT + kb + cu * 8;
        cpa16(sb + A_OFF + sw, g_A + go);
    }
#pragma unroll
    for (int i = 0; i < 4; i++) {               // W: 1024 16B units (4 gates x 32 rows)
        int u = tid + i * 256;
        int row = u >> 3, cu = u & 7;           // row 0..127: gate = row>>5, n = row&31
        uint32_t sw = (uint32_t)(row * 128 + ((cu ^ (row & 7)) << 4));
        size_t go = ((size_t)(row >> 5) * FFD + n0 + (row & 31)) * KTOT + kb + cu * 8;
        cpa16(sb + WP_OFF + sw, g_W + go);
    }
}

__global__ __launch_bounds__(256, 2)
void lstm_gemm_kernel(const float* __restrict__ c0, float* __restrict__ hout,
                      const float* __restrict__ bi, const float* __restrict__ bf,
                      const float* __restrict__ bg, const float* __restrict__ bo)
{
    extern __shared__ __align__(1024) char smem[];
    const uint32_t base = smem_u32(smem);
    const int tid = threadIdx.x;
    const int wid = tid >> 5;
    const int lane = tid & 31;
    const int warp_m = wid & 3;    // 4 warps over M (32 rows each)
    const int warp_n = wid >> 2;   // 2 warps over N (16 cols per gate each)
    const int m0 = blockIdx.y * 128;
    const int n0 = blockIdx.x * 32;

    const int quad = lane >> 3, rr = lane & 7;
    const int rowA0 = warp_m * 32 + (quad & 1) * 8 + rr;      // + mi*16
    const int rowA1 = rowA0 + 16;
    const int chA = quad >> 1;
    const int rowB  = warp_n * 16 + (quad >> 1) * 8 + rr;     // within 32-row gate slab
    const int chB = quad & 1;
    const int rA7 = rowA0 & 7;
    const int rB7 = rowB & 7;

    float acc[4][2][2][4];
#pragma unroll
    for (int g = 0; g < 4; g++)
#pragma unroll
        for (int mi = 0; mi < 2; mi++)
#pragma unroll
            for (int ni = 0; ni < 2; ni++)
#pragma unroll
                for (int q = 0; q < 4; q++) acc[g][mi][ni][q] = 0.0f;

    // prologue: chunks 0,1
    fill_stage(base + 0 * STAGE_SZ, m0, n0, 0, tid);   CPA_COMMIT();
    fill_stage(base + 1 * STAGE_SZ, m0, n0, 64, tid);  CPA_COMMIT();

    const int NCH = KTOT / 64;  // 64
    int sidx = 0;               // stage index of chunk c (mod 3)
#pragma unroll 1
    for (int c = 0; c < NCH; c++) {
        CPA_WAIT1();        // fill(c) complete (only fill(c+1) may be pending)
        __syncthreads();    // data visibility + all warps done with chunk c-1

        // refill stage (c+2)%3 == (c-1)%3 — safe after the barrier above
        if (c + 2 < NCH) {
            int ps = sidx + 2; if (ps >= 3) ps -= 3;
            fill_stage(base + ps * STAGE_SZ, m0, n0, (c + 2) * 64, tid);
        }
        CPA_COMMIT();       // always commit (group accounting)

        const uint32_t sb = base + sidx * STAGE_SZ;
        const uint32_t Ab = sb + A_OFF, Wb = sb + WP_OFF;

        uint32_t afrag[2][8], bfrag[2][4];

        // prime: A(ks=0), B(ks=0, g=0)
        {
            int u = chA;
            ldsm4(&afrag[0][0], Ab + rowA0 * 128 + ((u ^ rA7) << 4));
            ldsm4(&afrag[0][4], Ab + rowA1 * 128 + ((u ^ rA7) << 4));
            int ub = chB;
            ldsm4(&bfrag[0][0], Wb + rowB * 128 + ((ub ^ rB7) << 4));
        }

#pragma unroll
        for (int ks = 0; ks < 4; ks++) {
            const int ap = ks & 1;
#pragma unroll
            for (int g = 0; g < 4; g++) {
                const int bp = (ks * 4 + g) & 1;
                // prefetch next fragments before issuing MMAs
                if (g < 3) {
                    int row = (g + 1) * 32 + rowB;
                    int ub = ks * 2 + chB;
                    ldsm4(&bfrag[bp ^ 1][0], Wb + row * 128 + ((ub ^ rB7) << 4));
                } else if (ks < 3) {
                    int ua = (ks + 1) * 2 + chA;
                    ldsm4(&afrag[ap ^ 1][0], Ab + rowA0 * 128 + ((ua ^ rA7) << 4));
                    ldsm4(&afrag[ap ^ 1][4], Ab + rowA1 * 128 + ((ua ^ rA7) << 4));
                    int ub = (ks + 1) * 2 + chB;
                    ldsm4(&bfrag[bp ^ 1][0], Wb + rowB * 128 + ((ub ^ rB7) << 4));
                }
                mma16816(acc[g][0][0], &afrag[ap][0], &bfrag[bp][0]);
                mma16816(acc[g][0][1], &afrag[ap][0], &bfrag[bp][2]);
                mma16816(acc[g][1][0], &afrag[ap][4], &bfrag[bp][0]);
                mma16816(acc[g][1][1], &afrag[ap][4], &bfrag[bp][2]);
            }
        }
        if (++sidx >= 3) sidx = 0;
    }

    // ---- fused LSTM epilogue: acc[g] all live in this thread for same (m,n)
    const int row0 = m0 + warp_m * 32 + (lane >> 2);
    const int col0 = n0 + warp_n * 16 + (lane & 3) * 2;

#pragma unroll
    for (int ni = 0; ni < 2; ni++) {
        const int cc = col0 + ni * 8;
        float2 b_i = *(const float2*)(bi + cc);
        float2 b_f = *(const float2*)(bf + cc);
        float2 b_g = *(const float2*)(bg + cc);
        float2 b_o = *(const float2*)(bo + cc);
#pragma unroll
        for (int mi = 0; mi < 2; mi++) {
#pragma unroll
            for (int half = 0; half < 2; half++) {   // q{0,1} row r, q{2,3} row r+8
                int r = row0 + mi * 16 + half * 8;
                float2 cv = *(const float2*)(c0 + (size_t)r * FFD + cc);
                float out[2];
#pragma unroll
                for (int q = 0; q < 2; q++) {
                    float vi = acc[0][mi][ni][half * 2 + q] + (q ? b_i.y : b_i.x);
                    float vf = acc[1][mi][ni][half * 2 + q] + (q ? b_f.y : b_f.x);
                    float vg = acc[2][mi][ni][half * 2 + q] + (q ? b_g.y : b_g.x);
                    float vo = acc[3][mi][ni][half * 2 + q] + (q ? b_o.y : b_o.x);
                    float ig = 1.0f / (1.0f + expf(-vi));
                    float fg = 1.0f / (1.0f + expf(-vf));
                    float gg = tanhf(vg);
                    float og = 1.0f / (1.0f + expf(-vo));
                    float ccell = fg * (q ? cv.y : cv.x) + ig * gg;
                    out[q] = og * tanhf(ccell);
                }
                *(float2*)(hout + (size_t)r * FFD + cc) = make_float2(out[0], out[1]);
            }
        }
    }
}

// ---------------- kernel_launch ---------------------------------------------
// inputs: behavior, h0, c0, Wi_h, Wi_x, bi, Wf_h, Wf_x, bf, Wg_h, Wg_x, bg,
//         Wo_h, Wo_x, bo
extern "C" void kernel_launch(void* const* d_in, const int* in_sizes, int n_in,
                              void* d_out, int out_size)
{
    const float* behavior = (const float*)d_in[0];
    const float* h0       = (const float*)d_in[1];
    const float* c0       = (const float*)d_in[2];
    const float* Wi_h = (const float*)d_in[3];
    const float* Wi_x = (const float*)d_in[4];
    const float* bi   = (const float*)d_in[5];
    const float* Wf_h = (const float*)d_in[6];
    const float* Wf_x = (const float*)d_in[7];
    const float* bf   = (const float*)d_in[8];
    const float* Wg_h = (const float*)d_in[9];
    const float* Wg_x = (const float*)d_in[10];
    const float* bg   = (const float*)d_in[11];
    const float* Wo_h = (const float*)d_in[12];
    const float* Wo_x = (const float*)d_in[13];
    const float* bo   = (const float*)d_in[14];
    float* hout = (float*)d_out;

    cudaFuncSetAttribute(lstm_gemm_kernel,
                         cudaFuncAttributeMaxDynamicSharedMemorySize, SMEM_TOTAL);

    conv_AW_kernel<<<36864, 256>>>(h0, behavior,
                                   Wi_h, Wi_x, Wf_h, Wf_x,
                                   Wg_h, Wg_x, Wo_h, Wo_x);
    lstm_gemm_kernel<<<dim3(FFD / 32, NN / 128), 256, SMEM_TOTAL>>>(
        c0, hout, bi, bf, bg, bo);
}

// round 13
// speedup vs baseline: 1.1022x; 1.1022x over previous
#include <cuda_runtime.h>
#include <cuda_fp16.h>
#include <cstdint>
#include <math.h>

#define NN   4096
#define FFD  2048
#define KTOT 4096   // concat K: [h0 (2048) | behavior (2048)]
#define NTOT 8192   // 4 gates x 2048 columns

// ---------------- device scratch (no cudaMalloc allowed) -------------------
static __device__ __half g_A[(size_t)NN * KTOT];              // 33.5MB  A fp16 [m][k]
static __device__ __half g_W[(size_t)KTOT * NTOT];            // 67MB    W fp16 [k][n_global]

// ---------------- helpers ---------------------------------------------------
__device__ __forceinline__ uint32_t smem_u32(const void* p) {
    uint32_t a;
    asm("{ .reg .u64 t; cvta.to.shared.u64 t, %1; cvt.u32.u64 %0, t; }"
        : "=r"(a) : "l"(p));
    return a;
}
__device__ __forceinline__ void cpa16(uint32_t s, const void* g) {
    asm volatile("cp.async.cg.shared.global [%0], [%1], 16;" :: "r"(s), "l"(g));
}
#define CPA_COMMIT() asm volatile("cp.async.commit_group;" ::: "memory")
#define CPA_WAIT1()  asm volatile("cp.async.wait_group 1;" ::: "memory")

__device__ __forceinline__ void ldsm4(uint32_t* r, uint32_t addr) {
    asm volatile("ldmatrix.sync.aligned.m8n8.x4.shared.b16 {%0,%1,%2,%3}, [%4];"
                 : "=r"(r[0]), "=r"(r[1]), "=r"(r[2]), "=r"(r[3]) : "r"(addr));
}
__device__ __forceinline__ void ldsm4t(uint32_t* r, uint32_t addr) {
    asm volatile("ldmatrix.sync.aligned.m8n8.x4.trans.shared.b16 {%0,%1,%2,%3}, [%4];"
                 : "=r"(r[0]), "=r"(r[1]), "=r"(r[2]), "=r"(r[3]) : "r"(addr));
}
__device__ __forceinline__ void mma16816(float* c, const uint32_t* a, const uint32_t* b) {
    asm volatile("mma.sync.aligned.m16n8k16.row.col.f32.f16.f16.f32 "
                 "{%0,%1,%2,%3}, {%4,%5,%6,%7}, {%8,%9}, {%0,%1,%2,%3};"
                 : "+f"(c[0]), "+f"(c[1]), "+f"(c[2]), "+f"(c[3])
                 : "r"(a[0]), "r"(a[1]), "r"(a[2]), "r"(a[3]),
                   "r"(b[0]), "r"(b[1]));
}

// ---------------- merged pre-pass: A convert + W convert (both streaming) ---
// blocks [0, 4096):      A = [h0 | behavior] -> fp16, 4 float4 per thread
// blocks [4096, 12288):  W -> fp16 [k][n_global], pure elementwise, MLP=4
__global__ __launch_bounds__(256)
void conv_AW_kernel(const float* __restrict__ h0, const float* __restrict__ beh,
                    const float* Wi_h, const float* Wi_x,
                    const float* Wf_h, const float* Wf_x,
                    const float* Wg_h, const float* Wg_x,
                    const float* Wo_h, const float* Wo_x)
{
    const int b = blockIdx.x;
    const int tid = threadIdx.x;

    if (b < 4096) {
        // ---- A conversion ----
#pragma unroll
        for (int i = 0; i < 4; i++) {
            size_t e = ((size_t)b * 1024 + i * 256 + tid) * 4;
            int m = (int)(e >> 12);
            int k = (int)(e & 4095);
            const float* src = (k < 2048) ? (h0 + (size_t)m * 2048 + k)
                                          : (beh + (size_t)m * 2048 + (k - 2048));
            float4 v = *(const float4*)src;
            __half2* dh = (__half2*)(g_A + e);
            dh[0] = __halves2half2(__float2half_rn(v.x), __float2half_rn(v.y));
            dh[1] = __halves2half2(__float2half_rn(v.z), __float2half_rn(v.w));
        }
        return;
    }

    // ---- W conversion: src [K=2048][N=2048] fp32 -> g_W[isx*2048+k][g*2048+n]
    const float* srcs[8] = {Wi_h, Wi_x, Wf_h, Wf_x, Wg_h, Wg_x, Wo_h, Wo_x};
    const int bb = b - 4096;          // 0..8191
    const int z = bb >> 10;           // 0..7: source matrix
    const int blk = bb & 1023;        // 1024 blocks per source
    const int g = z >> 1, isx = z & 1;
    const float* __restrict__ src = srcs[z];

#pragma unroll
    for (int i = 0; i < 4; i++) {
        size_t e = ((size_t)blk * 1024 + i * 256 + tid) * 4;  // elem in [k][n] row-major
        int k = (int)(e >> 11);
        int n = (int)(e & 2047);
        float4 v = *(const float4*)(src + e);
        __half2* dh = (__half2*)(g_W + (size_t)(isx * 2048 + k) * NTOT + g * 2048 + n);
        dh[0] = __halves2half2(__float2half_rn(v.x), __float2half_rn(v.y));
        dh[1] = __halves2half2(__float2half_rn(v.z), __float2half_rn(v.w));
    }
}

// ---------------- fused 4-gate GEMM + LSTM epilogue -------------------------
// BM=128, BN=32 per gate (x4 gates), BK=64, 3 stages, 256 threads, 2 CTAs/SM.
// A smem: 128 rows x 128B (old swizzle). W smem: 64 k-rows x 256B (4 gates x
// 64B), unit-XOR swizzle; B fragments via ldmatrix.trans.
// fill is split into 4 quarters interleaved into the ks loop (port smoothing).
static constexpr int A_OFF    = 0;        // 16KB
static constexpr int WP_OFF   = 16384;    // 64 rows x 256B = 16KB
static constexpr int STAGE_SZ = 32768;    // 32KB
static constexpr int SMEM_TOTAL = 3 * STAGE_SZ;  // 96KB -> 2 CTAs/SM

// one quarter of a stage fill: 256 A units + 256 W units (1 + 1 per thread)
__device__ __forceinline__ void fill_quarter(uint32_t sb, int m0, int n0, int kb,
                                             int tid, int part) {
    {   // A: unit u_lin = tid + part*256 of 1024
        int u = tid + part * 256;
        int row = u >> 3, cu = u & 7;
        uint32_t sw = (uint32_t)(row * 128 + ((cu ^ (row & 7)) << 4));
        size_t go = (size_t)(m0 + row) * KTOT + kb + cu * 8;
        cpa16(sb + A_OFF + sw, g_A + go);
    }
    {   // W: unit u_lin of 1024; row = k (0..63), u = 16B unit (0..15)
        int ul = tid + part * 256;
        int row = ul >> 4, u = ul & 15;
        uint32_t sw = (uint32_t)(row * 256 + ((u ^ (row & 7)) << 4));
        size_t go = (size_t)(kb + row) * NTOT + (u >> 2) * 2048 + n0 + (u & 3) * 8;
        cpa16(sb + WP_OFF + sw, g_W + go);
    }
}
__device__ __forceinline__ void fill_stage(uint32_t sb, int m0, int n0, int kb, int tid) {
#pragma unroll
    for (int p = 0; p < 4; p++) fill_quarter(sb, m0, n0, kb, tid, p);
}

__global__ __launch_bounds__(256, 2)
void lstm_gemm_kernel(const float* __restrict__ c0, float* __restrict__ hout,
                      const float* __restrict__ bi, const float* __restrict__ bf,
                      const float* __restrict__ bg, const float* __restrict__ bo)
{
    extern __shared__ __align__(1024) char smem[];
    const uint32_t base = smem_u32(smem);
    const int tid = threadIdx.x;
    const int wid = tid >> 5;
    const int lane = tid & 31;
    const int warp_m = wid & 3;    // 4 warps over M (32 rows each)
    const int warp_n = wid >> 2;   // 2 warps over N (16 cols per gate each)
    const int m0 = blockIdx.y * 128;
    const int n0 = blockIdx.x * 32;

    const int quad = lane >> 3, rr = lane & 7;
    // A (unchanged): ldmatrix non-trans on [m][k] rows
    const int rowA0 = warp_m * 32 + (quad & 1) * 8 + rr;      // + mi*16
    const int rowA1 = rowA0 + 16;
    const int chA = quad >> 1;
    const int rA7 = rowA0 & 7;
    // B: ldmatrix.trans on [k][n] rows. lane q*8+r -> matrix q, k-row (q&1)*8+r,
    // n-half (q>>1). unit_base within gate slab = warp_n*2 + (q>>1).
    const int rowBk = (quad & 1) * 8 + rr;                    // + ks*16
    const int ubase = warp_n * 2 + (quad >> 1);

    float acc[4][2][2][4];
#pragma unroll
    for (int g = 0; g < 4; g++)
#pragma unroll
        for (int mi = 0; mi < 2; mi++)
#pragma unroll
            for (int ni = 0; ni < 2; ni++)
#pragma unroll
                for (int q = 0; q < 4; q++) acc[g][mi][ni][q] = 0.0f;

    // prologue: chunks 0,1 (full fills)
    fill_stage(base + 0 * STAGE_SZ, m0, n0, 0, tid);   CPA_COMMIT();
    fill_stage(base + 1 * STAGE_SZ, m0, n0, 64, tid);  CPA_COMMIT();

    const int NCH = KTOT / 64;  // 64
    int sidx = 0;               // stage index of chunk c (mod 3)
#pragma unroll 1
    for (int c = 0; c < NCH; c++) {
        CPA_WAIT1();        // fill(c) complete (only fill(c+1) may be pending)
        __syncthreads();    // data visibility + all warps done with chunk c-1

        const bool do_fill = (c + 2 < NCH);
        int ps = sidx + 2; if (ps >= 3) ps -= 3;
        const uint32_t psb = base + ps * STAGE_SZ;
        const int pkb = (c + 2) * 64;

        const uint32_t sb = base + sidx * STAGE_SZ;
        const uint32_t Ab = sb + A_OFF, Wb = sb + WP_OFF;

        uint32_t afrag[2][8], bfrag[2][4];

        // prime: A(ks=0), B(ks=0, g=0)
        {
            ldsm4(&afrag[0][0], Ab + rowA0 * 128 + ((chA ^ rA7) << 4));
            ldsm4(&afrag[0][4], Ab + rowA1 * 128 + ((chA ^ rA7) << 4));
            ldsm4t(&bfrag[0][0], Wb + rowBk * 256 + ((ubase ^ rr) << 4));
        }

#pragma unroll
        for (int ks = 0; ks < 4; ks++) {
            // interleaved quarter-fill of stage (c+2): spreads the write burst
            if (do_fill) fill_quarter(psb, m0, n0, pkb, tid, ks);

            const int ap = ks & 1;
#pragma unroll
            for (int g = 0; g < 4; g++) {
                const int bp = (ks * 4 + g) & 1;
                // prefetch next fragments before issuing MMAs
                if (g < 3) {
                    ldsm4t(&bfrag[bp ^ 1][0],
                           Wb + (ks * 16 + rowBk) * 256 +
                           ((((g + 1) * 4 + ubase) ^ rr) << 4));
                } else if (ks < 3) {
                    int ua = (ks + 1) * 2 + chA;
                    ldsm4(&afrag[ap ^ 1][0], Ab + rowA0 * 128 + ((ua ^ rA7) << 4));
                    ldsm4(&afrag[ap ^ 1][4], Ab + rowA1 * 128 + ((ua ^ rA7) << 4));
                    ldsm4t(&bfrag[bp ^ 1][0],
                           Wb + ((ks + 1) * 16 + rowBk) * 256 + ((ubase ^ rr) << 4));
                }
                mma16816(acc[g][0][0], &afrag[ap][0], &bfrag[bp][0]);
                mma16816(acc[g][0][1], &afrag[ap][0], &bfrag[bp][2]);
                mma16816(acc[g][1][0], &afrag[ap][4], &bfrag[bp][0]);
                mma16816(acc[g][1][1], &afrag[ap][4], &bfrag[bp][2]);
            }
        }
        CPA_COMMIT();       // one group per chunk (empty group OK near the end)
        if (++sidx >= 3) sidx = 0;
    }

    // ---- fused LSTM epilogue: acc[g] all live in this thread for same (m,n)
    const int row0 = m0 + warp_m * 32 + (lane >> 2);
    const int col0 = n0 + warp_n * 16 + (lane & 3) * 2;

#pragma unroll
    for (int ni = 0; ni < 2; ni++) {
        const int cc = col0 + ni * 8;
        float2 b_i = *(const float2*)(bi + cc);
        float2 b_f = *(const float2*)(bf + cc);
        float2 b_g = *(const float2*)(bg + cc);
        float2 b_o = *(const float2*)(bo + cc);
#pragma unroll
        for (int mi = 0; mi < 2; mi++) {
#pragma unroll
            for (int half = 0; half < 2; half++) {   // q{0,1} row r, q{2,3} row r+8
                int r = row0 + mi * 16 + half * 8;
                float2 cv = *(const float2*)(c0 + (size_t)r * FFD + cc);
                float out[2];
#pragma unroll
                for (int q = 0; q < 2; q++) {
                    float vi = acc[0][mi][ni][half * 2 + q] + (q ? b_i.y : b_i.x);
                    float vf = acc[1][mi][ni][half * 2 + q] + (q ? b_f.y : b_f.x);
                    float vg = acc[2][mi][ni][half * 2 + q] + (q ? b_g.y : b_g.x);
                    float vo = acc[3][mi][ni][half * 2 + q] + (q ? b_o.y : b_o.x);
                    float ig = 1.0f / (1.0f + expf(-vi));
                    float fg = 1.0f / (1.0f + expf(-vf));
                    float gg = tanhf(vg);
                    float og = 1.0f / (1.0f + expf(-vo));
                    float ccell = fg * (q ? cv.y : cv.x) + ig * gg;
                    out[q] = og * tanhf(ccell);
                }
                *(float2*)(hout + (size_t)r * FFD + cc) = make_float2(out[0], out[1]);
            }
        }
    }
}

// ---------------- kernel_launch ---------------------------------------------
// inputs: behavior, h0, c0, Wi_h, Wi_x, bi, Wf_h, Wf_x, bf, Wg_h, Wg_x, bg,
//         Wo_h, Wo_x, bo
extern "C" void kernel_launch(void* const* d_in, const int* in_sizes, int n_in,
                              void* d_out, int out_size)
{
    const float* behavior = (const float*)d_in[0];
    const float* h0       = (const float*)d_in[1];
    const float* c0       = (const float*)d_in[2];
    const float* Wi_h = (const float*)d_in[3];
    const float* Wi_x = (const float*)d_in[4];
    const float* bi   = (const float*)d_in[5];
    const float* Wf_h = (const float*)d_in[6];
    const float* Wf_x = (const float*)d_in[7];
    const float* bf   = (const float*)d_in[8];
    const float* Wg_h = (const float*)d_in[9];
    const float* Wg_x = (const float*)d_in[10];
    const float* bg   = (const float*)d_in[11];
    const float* Wo_h = (const float*)d_in[12];
    const float* Wo_x = (const float*)d_in[13];
    const float* bo   = (const float*)d_in[14];
    float* hout = (float*)d_out;

    cudaFuncSetAttribute(lstm_gemm_kernel,
                         cudaFuncAttributeMaxDynamicSharedMemorySize, SMEM_TOTAL);

    conv_AW_kernel<<<12288, 256>>>(h0, behavior,
                                   Wi_h, Wi_x, Wf_h, Wf_x,
                                   Wg_h, Wg_x, Wo_h, Wo_x);
    lstm_gemm_kernel<<<dim3(FFD / 32, NN / 128), 256, SMEM_TOTAL>>>(
        c0, hout, bi, bf, bg, bo);
}

// round 14
// speedup vs baseline: 1.1603x; 1.0527x over previous
#include <cuda_runtime.h>
#include <cuda_fp16.h>
#include <cstdint>
#include <math.h>

#define NN   4096
#define FFD  2048
#define KTOT 4096   // concat K: [h0 (2048) | behavior (2048)]
#define NTOT 8192   // 4 gates x 2048 columns

// ---------------- device scratch (no cudaMalloc allowed) -------------------
static __device__ __half g_A[(size_t)NN * KTOT];              // 33.5MB  A fp16 [m][k]
static __device__ __half g_W[(size_t)KTOT * NTOT];            // 67MB    W fp16 [k][n_global]

// ---------------- helpers ---------------------------------------------------
__device__ __forceinline__ uint32_t smem_u32(const void* p) {
    uint32_t a;
    asm("{ .reg .u64 t; cvta.to.shared.u64 t, %1; cvt.u32.u64 %0, t; }"
        : "=r"(a) : "l"(p));
    return a;
}
__device__ __forceinline__ void cpa16(uint32_t s, const void* g) {
    asm volatile("cp.async.cg.shared.global [%0], [%1], 16;" :: "r"(s), "l"(g));
}
#define CPA_COMMIT() asm volatile("cp.async.commit_group;" ::: "memory")
#define CPA_WAIT1()  asm volatile("cp.async.wait_group 1;" ::: "memory")

__device__ __forceinline__ void ldsm4(uint32_t* r, uint32_t addr) {
    asm volatile("ldmatrix.sync.aligned.m8n8.x4.shared.b16 {%0,%1,%2,%3}, [%4];"
                 : "=r"(r[0]), "=r"(r[1]), "=r"(r[2]), "=r"(r[3]) : "r"(addr));
}
__device__ __forceinline__ void ldsm4t(uint32_t* r, uint32_t addr) {
    asm volatile("ldmatrix.sync.aligned.m8n8.x4.trans.shared.b16 {%0,%1,%2,%3}, [%4];"
                 : "=r"(r[0]), "=r"(r[1]), "=r"(r[2]), "=r"(r[3]) : "r"(addr));
}
__device__ __forceinline__ void mma16816(float* c, const uint32_t* a, const uint32_t* b) {
    asm volatile("mma.sync.aligned.m16n8k16.row.col.f32.f16.f16.f32 "
                 "{%0,%1,%2,%3}, {%4,%5,%6,%7}, {%8,%9}, {%0,%1,%2,%3};"
                 : "+f"(c[0]), "+f"(c[1]), "+f"(c[2]), "+f"(c[3])
                 : "r"(a[0]), "r"(a[1]), "r"(a[2]), "r"(a[3]),
                   "r"(b[0]), "r"(b[1]));
}

// ---------------- merged pre-pass: A convert + W convert (both streaming) ---
__global__ __launch_bounds__(256)
void conv_AW_kernel(const float* __restrict__ h0, const float* __restrict__ beh,
                    const float* Wi_h, const float* Wi_x,
                    const float* Wf_h, const float* Wf_x,
                    const float* Wg_h, const float* Wg_x,
                    const float* Wo_h, const float* Wo_x)
{
    const int b = blockIdx.x;
    const int tid = threadIdx.x;

    if (b < 4096) {
        // ---- A conversion ----
#pragma unroll
        for (int i = 0; i < 4; i++) {
            size_t e = ((size_t)b * 1024 + i * 256 + tid) * 4;
            int m = (int)(e >> 12);
            int k = (int)(e & 4095);
            const float* src = (k < 2048) ? (h0 + (size_t)m * 2048 + k)
                                          : (beh + (size_t)m * 2048 + (k - 2048));
            float4 v = *(const float4*)src;
            __half2* dh = (__half2*)(g_A + e);
            dh[0] = __halves2half2(__float2half_rn(v.x), __float2half_rn(v.y));
            dh[1] = __halves2half2(__float2half_rn(v.z), __float2half_rn(v.w));
        }
        return;
    }

    // ---- W conversion: src [K=2048][N=2048] fp32 -> g_W[isx*2048+k][g*2048+n]
    const float* srcs[8] = {Wi_h, Wi_x, Wf_h, Wf_x, Wg_h, Wg_x, Wo_h, Wo_x};
    const int bb = b - 4096;          // 0..8191
    const int z = bb >> 10;           // 0..7: source matrix
    const int blk = bb & 1023;        // 1024 blocks per source
    const int g = z >> 1, isx = z & 1;
    const float* __restrict__ src = srcs[z];

#pragma unroll
    for (int i = 0; i < 4; i++) {
        size_t e = ((size_t)blk * 1024 + i * 256 + tid) * 4;  // elem in [k][n] row-major
        int k = (int)(e >> 11);
        int n = (int)(e & 2047);
        float4 v = *(const float4*)(src + e);
        __half2* dh = (__half2*)(g_W + (size_t)(isx * 2048 + k) * NTOT + g * 2048 + n);
        dh[0] = __halves2half2(__float2half_rn(v.x), __float2half_rn(v.y));
        dh[1] = __halves2half2(__float2half_rn(v.z), __float2half_rn(v.w));
    }
}

// ---------------- fused 4-gate GEMM + LSTM epilogue -------------------------
// BM=128, BN=32 per gate (x4 gates), BK=64, 3 stages, 256 threads, 2 CTAs/SM.
// All hot-loop addressing strength-reduced to precomputed registers.
static constexpr int A_OFF    = 0;        // 16KB
static constexpr int WP_OFF   = 16384;    // 64 rows x 256B = 16KB
static constexpr int STAGE_SZ = 32768;    // 32KB
static constexpr int SMEM_TOTAL = 3 * STAGE_SZ;  // 96KB -> 2 CTAs/SM

__global__ __launch_bounds__(256, 2)
void lstm_gemm_kernel(const float* __restrict__ c0, float* __restrict__ hout,
                      const float* __restrict__ bi, const float* __restrict__ bf,
                      const float* __restrict__ bg, const float* __restrict__ bo)
{
    extern __shared__ __align__(1024) char smem[];
    const uint32_t base = smem_u32(smem);
    const int tid = threadIdx.x;
    const int wid = tid >> 5;
    const int lane = tid & 31;
    const int warp_m = wid & 3;    // 4 warps over M (32 rows each)
    const int warp_n = wid >> 2;   // 2 warps over N (16 cols per gate each)
    const int m0 = blockIdx.y * 128;
    const int n0 = blockIdx.x * 32;

    const int quad = lane >> 3, rr = lane & 7;
    const int rowA0 = warp_m * 32 + (quad & 1) * 8 + rr;      // + mi*16
    const int rowA1 = rowA0 + 16;
    const int chA = quad >> 1;
    const int rA7 = rowA0 & 7;
    const int rowBk = (quad & 1) * 8 + rr;                    // + ks*16
    const int ubase = warp_n * 2 + (quad >> 1);

    // ---- precomputed ldsm offsets (registers) ----
    uint32_t au[4], bu[4];
#pragma unroll
    for (int ks = 0; ks < 4; ks++) au[ks] = (uint32_t)(((ks * 2 + chA) ^ rA7) << 4);
#pragma unroll
    for (int g = 0; g < 4; g++)    bu[g]  = (uint32_t)(((g * 4 + ubase) ^ rr) << 4);
    const uint32_t aoff0 = (uint32_t)(rowA0 * 128);
    const uint32_t aoff1 = (uint32_t)(rowA1 * 128);
    const uint32_t boff  = (uint32_t)(rowBk * 256);

    // ---- precomputed fill addressing ----
    // A: row = tid>>3 (+32/part), cu = tid&7; row&7 invariant across parts.
    const uint32_t a_sm_base =
        (uint32_t)(A_OFF + (tid >> 3) * 128 + (((tid & 7) ^ ((tid >> 3) & 7)) << 4));
    // W: row = tid>>4 (+16/part), u = tid&15; row&7 invariant across parts.
    const uint32_t w_sm_base =
        (uint32_t)(WP_OFF + (tid >> 4) * 256 + (((tid & 15) ^ ((tid >> 4) & 7)) << 4));
    const __half* a_gp = g_A + (size_t)(m0 + (tid >> 3)) * KTOT + (tid & 7) * 8;
    const __half* w_gp = g_W + (size_t)(tid >> 4) * NTOT
                             + ((tid & 15) >> 2) * 2048 + n0 + ((tid & 15) & 3) * 8;

    float acc[4][2][2][4];
#pragma unroll
    for (int g = 0; g < 4; g++)
#pragma unroll
        for (int mi = 0; mi < 2; mi++)
#pragma unroll
            for (int ni = 0; ni < 2; ni++)
#pragma unroll
                for (int q = 0; q < 4; q++) acc[g][mi][ni][q] = 0.0f;

    // prologue: fill chunks 0,1 into stages 0,1
#pragma unroll
    for (int cc = 0; cc < 2; cc++) {
        const uint32_t sb = base + cc * STAGE_SZ;
        const __half* ga = a_gp + cc * 64;
        const __half* gw = w_gp + (size_t)(cc * 64) * NTOT;
#pragma unroll
        for (int p = 0; p < 4; p++) {
            cpa16(sb + a_sm_base + p * 4096, ga + (size_t)p * 32 * KTOT);
            cpa16(sb + w_sm_base + p * 4096, gw + (size_t)p * 16 * NTOT);
        }
        CPA_COMMIT();
    }

    // running fill pointers (point at chunk c+2 = 2 initially)
    const __half* a_run = a_gp + 128;
    const __half* w_run = w_gp + (size_t)128 * NTOT;

    const int NCH = KTOT / 64;  // 64
    int sidx = 0;               // stage of chunk c (mod 3)
#pragma unroll 1
    for (int c = 0; c < NCH; c++) {
        CPA_WAIT1();        // fill(c) complete (only fill(c+1) may be pending)
        __syncthreads();    // data visibility + all warps done with chunk c-1

        const bool do_fill = (c + 2 < NCH);
        int ps = sidx + 2; if (ps >= 3) ps -= 3;
        const uint32_t psa = base + ps * STAGE_SZ + a_sm_base;
        const uint32_t psw = base + ps * STAGE_SZ + w_sm_base;

        const uint32_t sb = base + sidx * STAGE_SZ;
        const uint32_t Ab = sb + A_OFF, Wb = sb + WP_OFF;

        uint32_t afrag[2][8], bfrag[2][4];

        // prime: A(ks=0), B(ks=0, g=0)
        ldsm4(&afrag[0][0], Ab + aoff0 + au[0]);
        ldsm4(&afrag[0][4], Ab + aoff1 + au[0]);
        ldsm4t(&bfrag[0][0], Wb + boff + bu[0]);

#pragma unroll
        for (int ks = 0; ks < 4; ks++) {
            // one interleaved quarter-fill of stage (c+2): smooth write burst
            if (do_fill) {
                cpa16(psa + ks * 4096, a_run + (size_t)ks * 32 * KTOT);
                cpa16(psw + ks * 4096, w_run + (size_t)ks * 16 * NTOT);
            }
            const int ap = ks & 1;
#pragma unroll
            for (int g = 0; g < 4; g++) {
                const int bp = (ks * 4 + g) & 1;
                if (g < 3) {
                    ldsm4t(&bfrag[bp ^ 1][0], Wb + boff + ks * 4096 + bu[g + 1]);
                } else if (ks < 3) {
                    ldsm4(&afrag[ap ^ 1][0], Ab + aoff0 + au[ks + 1]);
                    ldsm4(&afrag[ap ^ 1][4], Ab + aoff1 + au[ks + 1]);
                    ldsm4t(&bfrag[bp ^ 1][0], Wb + boff + (ks + 1) * 4096 + bu[0]);
                }
                mma16816(acc[g][0][0], &afrag[ap][0], &bfrag[bp][0]);
                mma16816(acc[g][0][1], &afrag[ap][0], &bfrag[bp][2]);
                mma16816(acc[g][1][0], &afrag[ap][4], &bfrag[bp][0]);
                mma16816(acc[g][1][1], &afrag[ap][4], &bfrag[bp][2]);
            }
        }
        CPA_COMMIT();       // one group per chunk
        a_run += 64;
        w_run += (size_t)64 * NTOT;
        if (++sidx >= 3) sidx = 0;
    }

    // ---- fused LSTM epilogue: acc[g] all live in this thread for same (m,n)
    const int row0 = m0 + warp_m * 32 + (lane >> 2);
    const int col0 = n0 + warp_n * 16 + (lane & 3) * 2;

#pragma unroll
    for (int ni = 0; ni < 2; ni++) {
        const int cc = col0 + ni * 8;
        float2 b_i = *(const float2*)(bi + cc);
        float2 b_f = *(const float2*)(bf + cc);
        float2 b_g = *(const float2*)(bg + cc);
        float2 b_o = *(const float2*)(bo + cc);
#pragma unroll
        for (int mi = 0; mi < 2; mi++) {
#pragma unroll
            for (int half = 0; half < 2; half++) {   // q{0,1} row r, q{2,3} row r+8
                int r = row0 + mi * 16 + half * 8;
                float2 cv = *(const float2*)(c0 + (size_t)r * FFD + cc);
                float out[2];
#pragma unroll
                for (int q = 0; q < 2; q++) {
                    float vi = acc[0][mi][ni][half * 2 + q] + (q ? b_i.y : b_i.x);
                    float vf = acc[1][mi][ni][half * 2 + q] + (q ? b_f.y : b_f.x);
                    float vg = acc[2][mi][ni][half * 2 + q] + (q ? b_g.y : b_g.x);
                    float vo = acc[3][mi][ni][half * 2 + q] + (q ? b_o.y : b_o.x);
                    float ig = 1.0f / (1.0f + expf(-vi));
                    float fg = 1.0f / (1.0f + expf(-vf));
                    float gg = tanhf(vg);
                    float og = 1.0f / (1.0f + expf(-vo));
                    float ccell = fg * (q ? cv.y : cv.x) + ig * gg;
                    out[q] = og * tanhf(ccell);
                }
                *(float2*)(hout + (size_t)r * FFD + cc) = make_float2(out[0], out[1]);
            }
        }
    }
}

// ---------------- kernel_launch ---------------------------------------------
// inputs: behavior, h0, c0, Wi_h, Wi_x, bi, Wf_h, Wf_x, bf, Wg_h, Wg_x, bg,
//         Wo_h, Wo_x, bo
extern "C" void kernel_launch(void* const* d_in, const int* in_sizes, int n_in,
                              void* d_out, int out_size)
{
    const float* behavior = (const float*)d_in[0];
    const float* h0       = (const float*)d_in[1];
    const float* c0       = (const float*)d_in[2];
    const float* Wi_h = (const float*)d_in[3];
    const float* Wi_x = (const float*)d_in[4];
    const float* bi   = (const float*)d_in[5];
    const float* Wf_h = (const float*)d_in[6];
    const float* Wf_x = (const float*)d_in[7];
    const float* bf   = (const float*)d_in[8];
    const float* Wg_h = (const float*)d_in[9];
    const float* Wg_x = (const float*)d_in[10];
    const float* bg   = (const float*)d_in[11];
    const float* Wo_h = (const float*)d_in[12];
    const float* Wo_x = (const float*)d_in[13];
    const float* bo   = (const float*)d_in[14];
    float* hout = (float*)d_out;

    cudaFuncSetAttribute(lstm_gemm_kernel,
                         cudaFuncAttributeMaxDynamicSharedMemorySize, SMEM_TOTAL);

    conv_AW_kernel<<<12288, 256>>>(h0, behavior,
                                   Wi_h, Wi_x, Wf_h, Wf_x,
                                   Wg_h, Wg_x, Wo_h, Wo_x);
    lstm_gemm_kernel<<<dim3(FFD / 32, NN / 128), 256, SMEM_TOTAL>>>(
        c0, hout, bi, bf, bg, bo);
}

// round 17
// speedup vs baseline: 1.1699x; 1.0083x over previous
#include <cuda_runtime.h>
#include <cuda_fp16.h>
#include <cstdint>
#include <math.h>

#define NN   4096
#define FFD  2048
#define KTOT 4096   // concat K: [h0 (2048) | behavior (2048)]
#define NTOT 8192   // 4 gates x 2048 columns

// ---------------- device scratch (no cudaMalloc allowed) -------------------
static __device__ __half g_A[(size_t)NN * KTOT];              // 33.5MB  A fp16 [m][k]
static __device__ __half g_W[(size_t)KTOT * NTOT];            // 67MB    W fp16 [k][n_global]

// ---------------- helpers ---------------------------------------------------
__device__ __forceinline__ uint32_t smem_u32(const void* p) {
    uint32_t a;
    asm("{ .reg .u64 t; cvta.to.shared.u64 t, %1; cvt.u32.u64 %0, t; }"
        : "=r"(a) : "l"(p));
    return a;
}
__device__ __forceinline__ void cpa16(uint32_t s, const void* g) {
    asm volatile("cp.async.cg.shared.global [%0], [%1], 16;" :: "r"(s), "l"(g));
}
#define CPA_COMMIT() asm volatile("cp.async.commit_group;" ::: "memory")
#define CPA_WAIT1()  asm volatile("cp.async.wait_group 1;" ::: "memory")

__device__ __forceinline__ void ldsm4(uint32_t* r, uint32_t addr) {
    asm volatile("ldmatrix.sync.aligned.m8n8.x4.shared.b16 {%0,%1,%2,%3}, [%4];"
                 : "=r"(r[0]), "=r"(r[1]), "=r"(r[2]), "=r"(r[3]) : "r"(addr));
}
__device__ __forceinline__ void ldsm4t(uint32_t* r, uint32_t addr) {
    asm volatile("ldmatrix.sync.aligned.m8n8.x4.trans.shared.b16 {%0,%1,%2,%3}, [%4];"
                 : "=r"(r[0]), "=r"(r[1]), "=r"(r[2]), "=r"(r[3]) : "r"(addr));
}
__device__ __forceinline__ void mma16816(float* c, const uint32_t* a, const uint32_t* b) {
    asm volatile("mma.sync.aligned.m16n8k16.row.col.f32.f16.f16.f32 "
                 "{%0,%1,%2,%3}, {%4,%5,%6,%7}, {%8,%9}, {%0,%1,%2,%3};"
                 : "+f"(c[0]), "+f"(c[1]), "+f"(c[2]), "+f"(c[3])
                 : "r"(a[0]), "r"(a[1]), "r"(a[2]), "r"(a[3]),
                   "r"(b[0]), "r"(b[1]));
}

// pack 8 fp32 -> 8 fp16 (uint4) for one 16B store
__device__ __forceinline__ uint4 pack8(float4 v0, float4 v1) {
    __half2 h0 = __halves2half2(__float2half_rn(v0.x), __float2half_rn(v0.y));
    __half2 h1 = __halves2half2(__float2half_rn(v0.z), __float2half_rn(v0.w));
    __half2 h2 = __halves2half2(__float2half_rn(v1.x), __float2half_rn(v1.y));
    __half2 h3 = __halves2half2(__float2half_rn(v1.z), __float2half_rn(v1.w));
    uint4 u;
    u.x = *(uint32_t*)&h0; u.y = *(uint32_t*)&h1;
    u.z = *(uint32_t*)&h2; u.w = *(uint32_t*)&h3;
    return u;
}

// ---------------- merged pre-pass: A convert + W convert (both streaming) ---
// blocks [0, 2048):     A: 4 units of 8 elems per thread (2x float4 -> one 16B)
//                       covers 2048 * 1024 * 8 = 16.78M = NN*KTOT  [R15 bug fix]
// blocks [2048, 6144):  W: 4 units of 8 elems per thread per source matrix
__global__ __launch_bounds__(256)
void conv_AW_kernel(const float* __restrict__ h0, const float* __restrict__ beh,
                    const float* Wi_h, const float* Wi_x,
                    const float* Wf_h, const float* Wf_x,
                    const float* Wg_h, const float* Wg_x,
                    const float* Wo_h, const float* Wo_x)
{
    const int b = blockIdx.x;
    const int tid = threadIdx.x;

    if (b < 2048) {
        // ---- A conversion: 4 x (2 float4 LDG + 1 uint4 STG) per thread ----
#pragma unroll
        for (int i = 0; i < 4; i++) {
            size_t e = ((size_t)b * 1024 + i * 256 + tid) * 8;   // 8-elem unit
            int m = (int)(e >> 12);
            int k = (int)(e & 4095);
            const float* src = (k < 2048) ? (h0 + (size_t)m * 2048 + k)
                                          : (beh + (size_t)m * 2048 + (k - 2048));
            float4 v0 = ((const float4*)src)[0];
            float4 v1 = ((const float4*)src)[1];
            *(uint4*)(g_A + e) = pack8(v0, v1);
        }
        return;
    }

    // ---- W conversion: src [K=2048][N=2048] fp32 -> g_W[isx*2048+k][g*2048+n]
    const float* srcs[8] = {Wi_h, Wi_x, Wf_h, Wf_x, Wg_h, Wg_x, Wo_h, Wo_x};
    const int bb = b - 2048;          // 0..4095
    const int z = bb >> 9;            // 0..7: source matrix
    const int blk = bb & 511;         // 512 blocks per source
    const int g = z >> 1, isx = z & 1;
    const float* __restrict__ src = srcs[z];

#pragma unroll
    for (int i = 0; i < 4; i++) {
        size_t e = ((size_t)blk * 1024 + i * 256 + tid) * 8;    // 8-elem unit in [k][n]
        int k = (int)(e >> 11);
        int n = (int)(e & 2047);
        float4 v0 = ((const float4*)(src + e))[0];
        float4 v1 = ((const float4*)(src + e))[1];
        *(uint4*)(g_W + (size_t)(isx * 2048 + k) * NTOT + g * 2048 + n) = pack8(v0, v1);
    }
}

// ---------------- fused 4-gate GEMM + LSTM epilogue -------------------------
// BM=128, BN=32 per gate (x4 gates), BK=64, 3 stages, 256 threads, 2 CTAs/SM.
static constexpr int A_OFF    = 0;        // 16KB
static constexpr int WP_OFF   = 16384;    // 64 rows x 256B = 16KB
static constexpr int STAGE_SZ = 32768;    // 32KB
static constexpr int SMEM_TOTAL = 3 * STAGE_SZ;  // 96KB -> 2 CTAs/SM

__global__ __launch_bounds__(256, 2)
void lstm_gemm_kernel(const float* __restrict__ c0, float* __restrict__ hout,
                      const float* __restrict__ bi, const float* __restrict__ bf,
                      const float* __restrict__ bg, const float* __restrict__ bo)
{
    extern __shared__ __align__(1024) char smem[];
    const uint32_t base = smem_u32(smem);
    const int tid = threadIdx.x;
    const int wid = tid >> 5;
    const int lane = tid & 31;
    const int warp_m = wid & 3;    // 4 warps over M (32 rows each)
    const int warp_n = wid >> 2;   // 2 warps over N (16 cols per gate each)
    const int m0 = blockIdx.y * 128;
    const int n0 = blockIdx.x * 32;

    const int quad = lane >> 3, rr = lane & 7;
    const int rowA0 = warp_m * 32 + (quad & 1) * 8 + rr;      // + mi*16
    const int rowA1 = rowA0 + 16;
    const int chA = quad >> 1;
    const int rA7 = rowA0 & 7;
    const int rowBk = (quad & 1) * 8 + rr;                    // + ks*16
    const int ubase = warp_n * 2 + (quad >> 1);

    // ---- precomputed ldsm offsets (registers) ----
    uint32_t au[4], bu[4];
#pragma unroll
    for (int ks = 0; ks < 4; ks++) au[ks] = (uint32_t)(((ks * 2 + chA) ^ rA7) << 4);
#pragma unroll
    for (int g = 0; g < 4; g++)    bu[g]  = (uint32_t)(((g * 4 + ubase) ^ rr) << 4);
    const uint32_t aoff0 = (uint32_t)(rowA0 * 128);
    const uint32_t aoff1 = (uint32_t)(rowA1 * 128);
    const uint32_t boff  = (uint32_t)(rowBk * 256);

    // ---- precomputed fill addressing ----
    const uint32_t a_sm_base =
        (uint32_t)(A_OFF + (tid >> 3) * 128 + (((tid & 7) ^ ((tid >> 3) & 7)) << 4));
    const uint32_t w_sm_base =
        (uint32_t)(WP_OFF + (tid >> 4) * 256 + (((tid & 15) ^ ((tid >> 4) & 7)) << 4));
    const __half* a_gp = g_A + (size_t)(m0 + (tid >> 3)) * KTOT + (tid & 7) * 8;
    const __half* w_gp = g_W + (size_t)(tid >> 4) * NTOT
                             + ((tid & 15) >> 2) * 2048 + n0 + ((tid & 15) & 3) * 8;

    float acc[4][2][2][4];
#pragma unroll
    for (int g = 0; g < 4; g++)
#pragma unroll
        for (int mi = 0; mi < 2; mi++)
#pragma unroll
            for (int ni = 0; ni < 2; ni++)
#pragma unroll
                for (int q = 0; q < 4; q++) acc[g][mi][ni][q] = 0.0f;

    // prologue: fill chunks 0,1 into stages 0,1
#pragma unroll
    for (int cc = 0; cc < 2; cc++) {
        const uint32_t sb = base + cc * STAGE_SZ;
        const __half* ga = a_gp + cc * 64;
        const __half* gw = w_gp + (size_t)(cc * 64) * NTOT;
#pragma unroll
        for (int p = 0; p < 4; p++) {
            cpa16(sb + a_sm_base + p * 4096, ga + (size_t)p * 32 * KTOT);
            cpa16(sb + w_sm_base + p * 4096, gw + (size_t)p * 16 * NTOT);
        }
        CPA_COMMIT();
    }

    // running fill pointers (point at chunk c+2 = 2 initially)
    const __half* a_run = a_gp + 128;
    const __half* w_run = w_gp + (size_t)128 * NTOT;

    const int NCH = KTOT / 64;  // 64
    int sidx = 0;               // stage of chunk c (mod 3)
#pragma unroll 1
    for (int c = 0; c < NCH; c++) {
        CPA_WAIT1();        // fill(c) complete (only fill(c+1) may be pending)
        __syncthreads();    // data visibility + all warps done with chunk c-1

        const bool do_fill = (c + 2 < NCH);
        int ps = sidx + 2; if (ps >= 3) ps -= 3;
        const uint32_t psa = base + ps * STAGE_SZ + a_sm_base;
        const uint32_t psw = base + ps * STAGE_SZ + w_sm_base;

        const uint32_t sb = base + sidx * STAGE_SZ;
        const uint32_t Ab = sb + A_OFF, Wb = sb + WP_OFF;

        uint32_t afrag[2][8], bfrag[2][4];

        // prime: A(ks=0), B(ks=0, g=0)
        ldsm4(&afrag[0][0], Ab + aoff0 + au[0]);
        ldsm4(&afrag[0][4], Ab + aoff1 + au[0]);
        ldsm4t(&bfrag[0][0], Wb + boff + bu[0]);

#pragma unroll
        for (int ks = 0; ks < 4; ks++) {
            // one interleaved quarter-fill of stage (c+2): smooth write burst
            if (do_fill) {
                cpa16(psa + ks * 4096, a_run + (size_t)ks * 32 * KTOT);
                cpa16(psw + ks * 4096, w_run + (size_t)ks * 16 * NTOT);
            }
            const int ap = ks & 1;
#pragma unroll
            for (int g = 0; g < 4; g++) {
                const int bp = (ks * 4 + g) & 1;
                if (g == 2 && ks < 3) {
                    // A prefetch one gate early: +1 MMA-slot of latency cover
                    ldsm4(&afrag[ap ^ 1][0], Ab + aoff0 + au[ks + 1]);
                    ldsm4(&afrag[ap ^ 1][4], Ab + aoff1 + au[ks + 1]);
                }
                if (g < 3) {
                    ldsm4t(&bfrag[bp ^ 1][0], Wb + boff + ks * 4096 + bu[g + 1]);
                } else if (ks < 3) {
                    ldsm4t(&bfrag[bp ^ 1][0], Wb + boff + (ks + 1) * 4096 + bu[0]);
                }
                mma16816(acc[g][0][0], &afrag[ap][0], &bfrag[bp][0]);
                mma16816(acc[g][0][1], &afrag[ap][0], &bfrag[bp][2]);
                mma16816(acc[g][1][0], &afrag[ap][4], &bfrag[bp][0]);
                mma16816(acc[g][1][1], &afrag[ap][4], &bfrag[bp][2]);
            }
        }
        CPA_COMMIT();       // one group per chunk
        a_run += 64;
        w_run += (size_t)64 * NTOT;
        if (++sidx >= 3) sidx = 0;
    }

    // ---- fused LSTM epilogue: acc[g] all live in this thread for same (m,n)
    const int row0 = m0 + warp_m * 32 + (lane >> 2);
    const int col0 = n0 + warp_n * 16 + (lane & 3) * 2;

#pragma unroll
    for (int ni = 0; ni < 2; ni++) {
        const int cc = col0 + ni * 8;
        float2 b_i = *(const float2*)(bi + cc);
        float2 b_f = *(const float2*)(bf + cc);
        float2 b_g = *(const float2*)(bg + cc);
        float2 b_o = *(const float2*)(bo + cc);
#pragma unroll
        for (int mi = 0; mi < 2; mi++) {
#pragma unroll
            for (int half = 0; half < 2; half++) {   // q{0,1} row r, q{2,3} row r+8
                int r = row0 + mi * 16 + half * 8;
                float2 cv = *(const float2*)(c0 + (size_t)r * FFD + cc);
                float out[2];
#pragma unroll
                for (int q = 0; q < 2; q++) {
                    float vi = acc[0][mi][ni][half * 2 + q] + (q ? b_i.y : b_i.x);
                    float vf = acc[1][mi][ni][half * 2 + q] + (q ? b_f.y : b_f.x);
                    float vg = acc[2][mi][ni][half * 2 + q] + (q ? b_g.y : b_g.x);
                    float vo = acc[3][mi][ni][half * 2 + q] + (q ? b_o.y : b_o.x);
                    float ig = 1.0f / (1.0f + expf(-vi));
                    float fg = 1.0f / (1.0f + expf(-vf));
                    float gg = tanhf(vg);
                    float og = 1.0f / (1.0f + expf(-vo));
                    float ccell = fg * (q ? cv.y : cv.x) + ig * gg;
                    out[q] = og * tanhf(ccell);
                }
                *(float2*)(hout + (size_t)r * FFD + cc) = make_float2(out[0], out[1]);
            }
        }
    }
}

// ---------------- kernel_launch ---------------------------------------------
// inputs: behavior, h0, c0, Wi_h, Wi_x, bi, Wf_h, Wf_x, bf, Wg_h, Wg_x, bg,
//         Wo_h, Wo_x, bo
extern "C" void kernel_launch(void* const* d_in, const int* in_sizes, int n_in,
                              void* d_out, int out_size)
{
    const float* behavior = (const float*)d_in[0];
    const float* h0       = (const float*)d_in[1];
    const float* c0       = (const float*)d_in[2];
    const float* Wi_h = (const float*)d_in[3];
    const float* Wi_x = (const float*)d_in[4];
    const float* bi   = (const float*)d_in[5];
    const float* Wf_h = (const float*)d_in[6];
    const float* Wf_x = (const float*)d_in[7];
    const float* bf   = (const float*)d_in[8];
    const float* Wg_h = (const float*)d_in[9];
    const float* Wg_x = (const float*)d_in[10];
    const float* bg   = (const float*)d_in[11];
    const float* Wo_h = (const float*)d_in[12];
    const float* Wo_x = (const float*)d_in[13];
    const float* bo   = (const float*)d_in[14];
    float* hout = (float*)d_out;

    cudaFuncSetAttribute(lstm_gemm_kernel,
                         cudaFuncAttributeMaxDynamicSharedMemorySize, SMEM_TOTAL);

    conv_AW_kernel<<<6144, 256>>>(h0, behavior,
                                  Wi_h, Wi_x, Wf_h, Wf_x,
                                  Wg_h, Wg_x, Wo_h, Wo_x);
    lstm_gemm_kernel<<<dim3(FFD / 32, NN / 128), 256, SMEM_TOTAL>>>(
        c0, hout, bi, bf, bg, bo);
}